// round 13
// baseline (speedup 1.0000x reference)
#include <cuda_runtime.h>
#include <math.h>

// HG2Vec fused loss, v13 = v12 + decoupled L2 prefetch of the next position.
// Warp per (position, context-half): 35 dots, 17 rows read ONCE per warp
// (34 row-reads/position through l1tex vs 55 in the v6 family).
//  - NEW: during each iteration's reduction epilogue (the memory-idle phase),
//    lanes 0..9 issue prefetch.global.L2 for all 17 rows of the NEXT position
//    (128B stride across each 1200B row). No destination registers, no sync:
//    DRAM service for iteration k+1 overlaps the epilogue of iteration k, and
//    the demand LDGs upgrade from DRAM (~577cyc) to L2 (~240cyc) hits.
//  - 35 accumulators; a/b pair rotation (load c+1 before FMAs of c)
//  - scattered 32-value warp reduction + butterfly for sc2..4, lane-parallel
//    fast softplus (MUFU)
//  - next-iteration indices loaded into dead offset regs before the reduction
//  - __launch_bounds__(128,4): 16 warps/SM, grid 592 persistent
//  - last-block-done deterministic reduction, ticket self-resets (graph-safe)

#define ROWBYTES  1200u
#define NPOS      16384
#define NPAIR     8192            // 2 positions per CTA iteration
#define GRID      592             // 148 SMs * 4 resident CTAs
#define THREADS   128             // 4 warps: 2 positions x 2 c-halves

__device__ float        g_partial[GRID];
__device__ unsigned int g_ticket = 0;

#define PF_L2(PTR) \
    asm volatile("prefetch.global.L2 [%0];" :: "l"(PTR))

__global__ __launch_bounds__(THREADS, 4) void hg2vec_fused(
    const int*   __restrict__ pos_u,
    const int*   __restrict__ pos_v,
    const int*   __restrict__ info_v,
    const float* __restrict__ W_in,
    const float* __restrict__ W_out,
    const float* __restrict__ cmask,
    const float* __restrict__ sig_mask,
    const float* __restrict__ score_mask,
    float*       __restrict__ out)
{
    __shared__ float wloss[4];
    __shared__ bool  amLast;

    const int tid  = threadIdx.x;
    const int w    = tid >> 5;
    const int lane = tid & 31;
    const int grp  = w & 1;        // context half: c = grp*5 .. grp*5+4
    const int wpos = w >> 1;       // which of the 2 positions this iteration

    const char* __restrict__ Win_b  = (const char*)W_in;
    const char* __restrict__ Wout_b = (const char*)W_out;

    // ---- per-lane term coefficients for the 32-value scatter ----
    float t_pre = 1.f, t_sgn = 1.f, t_wt = 1.f;
    if (lane < 2) {
        t_pre = cmask[grp * 5 + lane];
    } else {
        const int i = (lane - 2) % 6;
        t_sgn = sig_mask[i];
        t_wt  = score_mask[i];
    }
    // aux coefficients for classically-reduced sc2..4 (evaluated on lanes 4..6)
    float a_pre = 0.f, a_wt = 0.f;
    if (lane >= 4 && lane < 7) {
        a_pre = cmask[grp * 5 + 2 + (lane - 4)];
        a_wt  = 1.f;
    }

    // per-lane prefetch byte offset within a row (lanes 0..9 cover 1200B)
    const unsigned pfo = (unsigned)lane * 128u;
    const bool     pfa = (lane < 10);

    float acc_loss = 0.f;

    int pp = blockIdx.x;

    // ---- prime offsets for the first position ----
    unsigned puo;
    unsigned pvo[5], ivo[6];
    {
        const int p = pp * 2 + wpos;
        puo = (unsigned)pos_u[p] * ROWBYTES;
#pragma unroll
        for (int c = 0; c < 5; c++)
            pvo[c] = (unsigned)pos_v[p * 10 + grp * 5 + c] * ROWBYTES;
#pragma unroll
        for (int i = 0; i < 6; i++)
            ivo[i] = (unsigned)info_v[p * 6 + i] * ROWBYTES;
    }

    while (pp < NPAIR) {
        const int pn = pp + GRID;

        // ---- 35 accumulators ----
        float sc[5];
        float ai[30];
#pragma unroll
        for (int c = 0; c < 5; c++) sc[c] = 0.f;
#pragma unroll
        for (int q = 0; q < 30; q++) ai[q] = 0.f;

        // ---- 3 d-chunks; each row read once by this warp ----
#pragma unroll
        for (int jj = 0; jj < 3; jj++) {
            const int j = lane + jj * 32;
            if (j < 75) {
                const unsigned jb = (unsigned)j * 16u;
                const float4 t4 = *(const float4*)(Wout_b + puo + jb);
                float4 f4[6];
#pragma unroll
                for (int i = 0; i < 6; i++)
                    f4[i] = *(const float4*)(Win_b + ivo[i] + jb);

                // a/b pair rotation: load c+1 before consuming c
                float4 ca = *(const float4*)(Win_b  + pvo[0] + jb);
                float4 cb = *(const float4*)(Wout_b + pvo[0] + jb);
#pragma unroll
                for (int c = 0; c < 5; c++) {
                    float4 na, nb;
                    if (c < 4) {
                        na = *(const float4*)(Win_b  + pvo[c + 1] + jb);
                        nb = *(const float4*)(Wout_b + pvo[c + 1] + jb);
                    }
                    sc[c] += ca.x * t4.x + ca.y * t4.y
                           + ca.z * t4.z + ca.w * t4.w;
#pragma unroll
                    for (int i = 0; i < 6; i++) {
                        ai[c * 6 + i] += cb.x * f4[i].x + cb.y * f4[i].y
                                       + cb.z * f4[i].z + cb.w * f4[i].w;
                    }
                    if (c < 4) { ca = na; cb = nb; }
                }
            }
        }

        // ---- offsets dead: load next iteration's indices now ----
        {
            const int pq = (pn < NPAIR) ? pn : 0;
            const int p2 = pq * 2 + wpos;
            puo = (unsigned)pos_u[p2] * ROWBYTES;
#pragma unroll
            for (int c = 0; c < 5; c++)
                pvo[c] = (unsigned)pos_v[p2 * 10 + grp * 5 + c] * ROWBYTES;
#pragma unroll
            for (int i = 0; i < 6; i++)
                ivo[i] = (unsigned)info_v[p2 * 6 + i] * ROWBYTES;
        }

        // ---- decoupled L2 prefetch of ALL next-position rows (no regs) ----
        // lanes 0..9 cover each 1200B row at 128B stride; DRAM service for
        // the next iteration overlaps the shuffle/MUFU epilogue below.
        if (pfa) {
            PF_L2(Wout_b + puo + pfo);
#pragma unroll
            for (int i = 0; i < 6; i++) PF_L2(Win_b + ivo[i] + pfo);
#pragma unroll
            for (int c = 0; c < 5; c++) {
                PF_L2(Win_b  + pvo[c] + pfo);
                PF_L2(Wout_b + pvo[c] + pfo);
            }
        }

        // ---- scattered 32-value warp reduction ----
        {
            float v0[16];
            {
                float a, b;
                a = sc[0]  + __shfl_xor_sync(0xffffffffu, sc[0],  16);
                b = ai[14] + __shfl_xor_sync(0xffffffffu, ai[14], 16);
                v0[0] = (lane & 16) ? b : a;
                a = sc[1]  + __shfl_xor_sync(0xffffffffu, sc[1],  16);
                b = ai[15] + __shfl_xor_sync(0xffffffffu, ai[15], 16);
                v0[1] = (lane & 16) ? b : a;
#pragma unroll
                for (int q = 2; q < 16; q++) {
                    a = ai[q - 2]  + __shfl_xor_sync(0xffffffffu, ai[q - 2],  16);
                    b = ai[q + 14] + __shfl_xor_sync(0xffffffffu, ai[q + 14], 16);
                    v0[q] = (lane & 16) ? b : a;
                }
            }
            float v1[8];
#pragma unroll
            for (int q = 0; q < 8; q++) {
                const float a = v0[q]     + __shfl_xor_sync(0xffffffffu, v0[q],     8);
                const float b = v0[q + 8] + __shfl_xor_sync(0xffffffffu, v0[q + 8], 8);
                v1[q] = (lane & 8) ? b : a;
            }
            float v2[4];
#pragma unroll
            for (int q = 0; q < 4; q++) {
                const float a = v1[q]     + __shfl_xor_sync(0xffffffffu, v1[q],     4);
                const float b = v1[q + 4] + __shfl_xor_sync(0xffffffffu, v1[q + 4], 4);
                v2[q] = (lane & 4) ? b : a;
            }
            float v3[2];
#pragma unroll
            for (int q = 0; q < 2; q++) {
                const float a = v2[q]     + __shfl_xor_sync(0xffffffffu, v2[q],     2);
                const float b = v2[q + 2] + __shfl_xor_sync(0xffffffffu, v2[q + 2], 2);
                v3[q] = (lane & 2) ? b : a;
            }
            float v4;
            {
                const float a = v3[0] + __shfl_xor_sync(0xffffffffu, v3[0], 1);
                const float b = v3[1] + __shfl_xor_sync(0xffffffffu, v3[1], 1);
                v4 = (lane & 1) ? b : a;
            }

            // classic butterfly for the 3 remaining score sums
#pragma unroll
            for (int off = 16; off; off >>= 1) {
                sc[2] += __shfl_xor_sync(0xffffffffu, sc[2], off);
                sc[3] += __shfl_xor_sync(0xffffffffu, sc[3], off);
                sc[4] += __shfl_xor_sync(0xffffffffu, sc[4], off);
            }

            // ---- lane-parallel loss terms ----
            const float x = fminf(fmaxf(v4 * t_pre, -10.f), 10.f) * t_sgn;
            acc_loss += __logf(1.f + __expf(-x)) * t_wt;

            const float sa = (lane == 4) ? sc[2] : ((lane == 5) ? sc[3] : sc[4]);
            const float xa = fminf(fmaxf(sa * a_pre, -10.f), 10.f);
            acc_loss += __logf(1.f + __expf(-xa)) * a_wt;
        }

        pp = pn;
    }

    // ---- block reduction ----
#pragma unroll
    for (int off = 16; off; off >>= 1)
        acc_loss += __shfl_xor_sync(0xffffffffu, acc_loss, off);
    if (lane == 0) wloss[w] = acc_loss;
    __syncthreads();

    if (tid == 0) {
        float s = wloss[0] + wloss[1] + wloss[2] + wloss[3];
        g_partial[blockIdx.x] = s;
        __threadfence();
        unsigned t = atomicAdd(&g_ticket, 1u);
        amLast = (t == GRID - 1);
    }
    __syncthreads();

    // ---- last block: deterministic fixed-order final sum ----
    if (amLast) {
        __shared__ float fs[THREADS];
        float v = 0.f;
        for (int i = tid; i < GRID; i += THREADS)
            v += __ldcg(&g_partial[i]);
        fs[tid] = v;
        __syncthreads();
#pragma unroll
        for (int st = THREADS / 2; st; st >>= 1) {
            if (tid < st) fs[tid] += fs[tid + st];
            __syncthreads();
        }
        if (tid == 0) {
            out[0] = fs[0];
            g_ticket = 0;            // reset for next graph replay
            __threadfence();
        }
    }
}

extern "C" void kernel_launch(void* const* d_in, const int* in_sizes, int n_in,
                              void* d_out, int out_size)
{
    const int*   pos_u  = (const int*)  d_in[0];
    const int*   pos_v  = (const int*)  d_in[1];
    const int*   info_v = (const int*)  d_in[2];
    const float* W_in   = (const float*)d_in[3];
    const float* W_out  = (const float*)d_in[4];
    const float* cmask  = (const float*)d_in[5];
    const float* sigm   = (const float*)d_in[6];
    const float* smask  = (const float*)d_in[7];

    hg2vec_fused<<<GRID, THREADS>>>(pos_u, pos_v, info_v, W_in, W_out,
                                    cmask, sigm, smask, (float*)d_out);
}